// round 11
// baseline (speedup 1.0000x reference)
#include <cuda_runtime.h>
#include <cuda_bf16.h>
#include <cstdint>

// ---------------- Problem constants ----------------
#define T_SEQ   2048
#define NEMBD   2048
#define NHEAD   16
#define KVLOW   512
#define QLOW    1024
#define ROPEHS  64
#define QKHS    576
#define LATD    1600
#define QTOT    9216
#define YTOT    8192
#define NPAD1   1664   // 1600 padded up to 13*128

typedef __nv_bfloat16 bf16;

// ---------------- Scratch (device globals; no allocations allowed) ----------------
__device__ float g_lat[(size_t)T_SEQ * LATD];
__device__ float g_qbuf[(size_t)T_SEQ * QTOT];
__device__ float g_scores[(size_t)NHEAD * T_SEQ * T_SEQ];

__device__ bf16 g_xhi[(size_t)T_SEQ * NEMBD];
__device__ bf16 g_xlo[(size_t)T_SEQ * NEMBD];
__device__ bf16 g_wqkvThi[(size_t)NPAD1 * NEMBD];
__device__ bf16 g_wqkvTlo[(size_t)NPAD1 * NEMBD];
__device__ bf16 g_cqhi[(size_t)T_SEQ * QLOW];
__device__ bf16 g_cqlo[(size_t)T_SEQ * QLOW];
__device__ bf16 g_wqdecThi[(size_t)QTOT * QLOW];
__device__ bf16 g_wqdecTlo[(size_t)QTOT * QLOW];
__device__ bf16 g_qhi[(size_t)T_SEQ * QTOT];
__device__ bf16 g_qlo[(size_t)T_SEQ * QTOT];
__device__ bf16 g_khi[(size_t)T_SEQ * QKHS];
__device__ bf16 g_klo[(size_t)T_SEQ * QKHS];
__device__ bf16 g_vThi[(size_t)KVLOW * T_SEQ];
__device__ bf16 g_vTlo[(size_t)KVLOW * T_SEQ];
__device__ bf16 g_attnhi[(size_t)NHEAD * T_SEQ * T_SEQ];
__device__ bf16 g_attnlo[(size_t)NHEAD * T_SEQ * T_SEQ];
__device__ bf16 g_yhi[(size_t)T_SEQ * YTOT];
__device__ bf16 g_ylo[(size_t)T_SEQ * YTOT];
__device__ bf16 g_woutThi[(size_t)NEMBD * YTOT];
__device__ bf16 g_woutTlo[(size_t)NEMBD * YTOT];

// ---------------- helpers ----------------
__device__ __forceinline__ void hlsplit(float v, bf16& h, bf16& l) {
    h = __float2bfloat16(v);
    l = __float2bfloat16(v - __bfloat162float(h));
}
__device__ __forceinline__ uint32_t smem_u32(const void* p) {
    uint32_t a;
    asm("{ .reg .u64 t; cvta.to.shared.u64 t, %1; cvt.u32.u64 %0, t; }" : "=r"(a) : "l"(p));
    return a;
}

#define CPA(dst, src) \
    asm volatile("cp.async.cg.shared.global [%0], [%1], 16;\n" :: "r"(dst), "l"(src))
#define CP_COMMIT() asm volatile("cp.async.commit_group;\n" ::: "memory")
#define CP_WAIT(N)  asm volatile("cp.async.wait_group %0;\n" :: "n"(N) : "memory")

#define LDSM4(r, addr) \
    asm volatile("ldmatrix.sync.aligned.m8n8.x4.shared.b16 {%0,%1,%2,%3}, [%4];" \
        : "=r"((r)[0]), "=r"((r)[1]), "=r"((r)[2]), "=r"((r)[3]) : "r"(addr))

#define MMA(d, a, b) \
    asm volatile("mma.sync.aligned.m16n8k16.row.col.f32.bf16.bf16.f32 " \
        "{%0,%1,%2,%3}, {%4,%5,%6,%7}, {%8,%9}, {%0,%1,%2,%3};" \
        : "+f"((d)[0]), "+f"((d)[1]), "+f"((d)[2]), "+f"((d)[3]) \
        : "r"((a)[0]), "r"((a)[1]), "r"((a)[2]), "r"((a)[3]), "r"((b)[0]), "r"((b)[1]))

// ---------------- Conversion bodies ----------------
__device__ __forceinline__ void convpack_body(const float* __restrict__ in,
                                              bf16* __restrict__ hi, bf16* __restrict__ lo,
                                              int R, int C, int ldin, size_t idx)
{
    int half = C >> 1;
    if (idx >= (size_t)R * half) return;
    int r = (int)(idx / half);
    int c = (int)(idx - (size_t)r * half) * 2;
    float v0 = in[(size_t)r * ldin + c];
    float v1 = in[(size_t)r * ldin + c + 1];
    bf16 h0, l0, h1, l1;
    hlsplit(v0, h0, l0); hlsplit(v1, h1, l1);
    *(__nv_bfloat162*)(hi + (size_t)r * C + c) = __nv_bfloat162(h0, h1);
    *(__nv_bfloat162*)(lo + (size_t)r * C + c) = __nv_bfloat162(l0, l1);
}

__device__ __forceinline__ void cvT_body(const float* __restrict__ in,
                                         bf16* __restrict__ hi, bf16* __restrict__ lo,
                                         int R, int C, int ldin, int bx, int by,
                                         int tid, float (*ts)[33])
{
    const int c0 = bx * 32, r0 = by * 32;
    const int j = tid & 31;
    #pragma unroll
    for (int q = 0; q < 4; q++) {
        int i = (tid >> 5) + q * 8;
        ts[j][i] = (c0 + j < C) ? in[(size_t)(r0 + i) * ldin + (c0 + j)] : 0.f;
    }
    __syncthreads();
    const int cl = tid >> 3, g = tid & 7;
    bf16 h[4], l[4];
    #pragma unroll
    for (int q = 0; q < 4; q++) hlsplit(ts[cl][g * 4 + q], h[q], l[q]);
    size_t base = (size_t)(c0 + cl) * R + r0 + g * 4;
    *(__nv_bfloat162*)(hi + base)     = __nv_bfloat162(h[0], h[1]);
    *(__nv_bfloat162*)(hi + base + 2) = __nv_bfloat162(h[2], h[3]);
    *(__nv_bfloat162*)(lo + base)     = __nv_bfloat162(l[0], l[1]);
    *(__nv_bfloat162*)(lo + base + 2) = __nv_bfloat162(l[2], l[3]);
}

// launch 0: x -> hi/lo
__global__ void conv_x(const float* __restrict__ x, bf16* __restrict__ hi, bf16* __restrict__ lo)
{
    convpack_body(x, hi, lo, T_SEQ, NEMBD, NEMBD, (size_t)blockIdx.x * 256 + threadIdx.x);
}
// launch 1: WqkvT
__global__ void conv_wqkv(const float* __restrict__ w, bf16* __restrict__ hi, bf16* __restrict__ lo)
{
    __shared__ float ts[32][33];
    cvT_body(w, hi, lo, NEMBD, LATD, LATD, blockIdx.x, blockIdx.y, threadIdx.x, ts);
}
// launch 2: fused WqdecT + WoutT
#define NQDBLK ((QTOT / 32) * (QLOW / 32))      // 9216
#define NWOBLK ((NEMBD / 32) * (YTOT / 32))     // 16384
__global__ void conv_w2(const float* __restrict__ wqdec, bf16* __restrict__ qdhi, bf16* __restrict__ qdlo,
                        const float* __restrict__ wout, bf16* __restrict__ wohi, bf16* __restrict__ wolo)
{
    __shared__ float ts[32][33];
    int b = blockIdx.x;
    if (b < NQDBLK) {
        cvT_body(wqdec, qdhi, qdlo, QLOW, QTOT, QTOT, b % (QTOT / 32), b / (QTOT / 32), threadIdx.x, ts);
    } else {
        b -= NQDBLK;
        cvT_body(wout, wohi, wolo, YTOT, NEMBD, NEMBD, b % (NEMBD / 32), b / (NEMBD / 32), threadIdx.x, ts);
    }
}
// launch 4: fused cq convpack + vT transpose (both read lat)
#define NCQBLK 4096                              // 2048*1024/2/256
#define NVTBLK ((KVLOW / 32) * (T_SEQ / 32))     // 1024
__global__ void conv_lat(const float* __restrict__ lat,
                         bf16* __restrict__ cqhi, bf16* __restrict__ cqlo,
                         bf16* __restrict__ vthi, bf16* __restrict__ vtlo)
{
    __shared__ float ts[32][33];
    int b = blockIdx.x;
    if (b < NCQBLK) {
        convpack_body(lat + (KVLOW + ROPEHS), cqhi, cqlo, T_SEQ, QLOW, LATD,
                      (size_t)b * 256 + threadIdx.x);
    } else {
        b -= NCQBLK;
        cvT_body(lat, vthi, vtlo, T_SEQ, KVLOW, LATD, b % (KVLOW / 32), b / (KVLOW / 32),
                 threadIdx.x, ts);
    }
}

// ---------------- RoPE + hi/lo pack of q and k ----------------
__global__ void rope_pack_kernel(const float* __restrict__ lat, const float* __restrict__ qbuf,
                                 const float* __restrict__ cosT, const float* __restrict__ sinT,
                                 bf16* __restrict__ khi, bf16* __restrict__ klo,
                                 bf16* __restrict__ qhi, bf16* __restrict__ qlo)
{
    const int t = blockIdx.x, tid = threadIdx.x;
    __shared__ float cs[ROPEHS], sn[ROPEHS];
    if (tid < ROPEHS) {
        cs[tid] = cosT[(size_t)t * ROPEHS + tid];
        sn[tid] = sinT[(size_t)t * ROPEHS + tid];
    }
    __syncthreads();

    const float* lrow = lat + (size_t)t * LATD;
    bf16* krh = khi + (size_t)t * QKHS;
    bf16* krl = klo + (size_t)t * QKHS;
    for (int p = tid; p < QKHS / 2; p += 256) {
        int e = p * 2;
        float v[2];
        #pragma unroll
        for (int u = 0; u < 2; u++) {
            int ee = e + u;
            if (ee < KVLOW) v[u] = lrow[ee];
            else {
                int i2 = ee - KVLOW;
                float xv = lrow[ee];
                v[u] = (i2 < 32) ? xv * cs[i2] - lrow[ee + 32] * sn[i2]
                                 : xv * cs[i2] + lrow[ee - 32] * sn[i2];
            }
        }
        bf16 h0, l0, h1, l1;
        hlsplit(v[0], h0, l0); hlsplit(v[1], h1, l1);
        *(__nv_bfloat162*)(krh + e) = __nv_bfloat162(h0, h1);
        *(__nv_bfloat162*)(krl + e) = __nv_bfloat162(l0, l1);
    }

    const float* qrow = qbuf + (size_t)t * QTOT;
    bf16* qrh = qhi + (size_t)t * QTOT;
    bf16* qrl = qlo + (size_t)t * QTOT;
    for (int p = tid; p < QTOT / 2; p += 256) {
        int e = p * 2;
        float v[2];
        #pragma unroll
        for (int u = 0; u < 2; u++) {
            int ee = e + u;
            int hh = ee / QKHS;
            int i = ee - hh * QKHS;
            if (i < KVLOW) v[u] = qrow[ee];
            else {
                int i2 = i - KVLOW;
                float xv = qrow[ee];
                v[u] = (i2 < 32) ? xv * cs[i2] - qrow[ee + 32] * sn[i2]
                                 : xv * cs[i2] + qrow[ee - 32] * sn[i2];
            }
        }
        bf16 h0, l0, h1, l1;
        hlsplit(v[0], h0, l0); hlsplit(v[1], h1, l1);
        *(__nv_bfloat162*)(qrh + e) = __nv_bfloat162(h0, h1);
        *(__nv_bfloat162*)(qrl + e) = __nv_bfloat162(l0, l1);
    }
}

// ---------------- Softmax -> hi/lo attn (zero-filled to 128-boundary) ----------------
__global__ __launch_bounds__(256)
void softmax_kernel(const float* __restrict__ scores,
                    bf16* __restrict__ ahi, bf16* __restrict__ alo)
{
    __shared__ float srow[T_SEQ];
    __shared__ float red[8];
    const int t = blockIdx.x, h = blockIdx.y, tid = threadIdx.x;
    const float* row = scores + ((size_t)h * T_SEQ + t) * T_SEQ;
    const int n = t + 1;

    float m = -3.4e38f;
    for (int s = tid; s < n; s += 256) { float v = row[s]; srow[s] = v; m = fmaxf(m, v); }
    #pragma unroll
    for (int o = 16; o; o >>= 1) m = fmaxf(m, __shfl_xor_sync(0xffffffffu, m, o));
    if ((tid & 31) == 0) red[tid >> 5] = m;
    __syncthreads();
    float mmax = red[0];
    #pragma unroll
    for (int i = 1; i < 8; i++) mmax = fmaxf(mmax, red[i]);
    __syncthreads();

    float sum = 0.f;
    for (int s = tid; s < n; s += 256) { float e = __expf(srow[s] - mmax); srow[s] = e; sum += e; }
    #pragma unroll
    for (int o = 16; o; o >>= 1) sum += __shfl_xor_sync(0xffffffffu, sum, o);
    if ((tid & 31) == 0) red[tid >> 5] = sum;
    __syncthreads();
    float total = 0.f;
    #pragma unroll
    for (int i = 0; i < 8; i++) total += red[i];
    const float inv = 1.f / total;

    bf16* rh = ahi + ((size_t)h * T_SEQ + t) * T_SEQ;
    bf16* rl = alo + ((size_t)h * T_SEQ + t) * T_SEQ;
    const int kpad = ((t >> 7) + 1) << 7;   // 128-granular for PV K truncation
    for (int p = tid; p < (kpad >> 1); p += 256) {
        int s0 = 2 * p;
        float v0 = (s0 <= t) ? srow[s0] * inv : 0.f;
        float v1 = (s0 + 1 <= t) ? srow[s0 + 1] * inv : 0.f;
        bf16 h0, l0, h1, l1;
        hlsplit(v0, h0, l0); hlsplit(v1, h1, l1);
        *(__nv_bfloat162*)(rh + s0) = __nv_bfloat162(h0, h1);
        *(__nv_bfloat162*)(rl + s0) = __nv_bfloat162(l0, l1);
    }
}

// ---------------- mma.sync GEMM: C = alpha * A * B^T ----------------
// CTA tile 128x128, 128 threads (4 warps, 2m x 2n of 64x64 warp tiles), BK=32,
// 3-stage smem pipeline, compact XOR-swizzled smem, 1 sync/chunk, 2 CTAs/SM.
// 64x64 warp tiles halve A/B fragment duplication (dup 2+2 vs 4+2) ->
// LDSM crossbar traffic drops ~33% below HMMA issue demand.
#define TILEB  8192                 // 128 rows x 64B
#define STAGEB (4 * TILEB)          // 32768: Ahi, Alo, Bhi, Blo
#define NSTAGE 3
#define SMEM_TOT (NSTAGE * STAGEB)  // 98304

template<int CSKIP, bool CK, int EPI>   // EPI: 0 -> f32 C, 1 -> hi/lo bf16 C
__global__ __launch_bounds__(128, 2)
void mmagemm(const bf16* __restrict__ Ahi, const bf16* __restrict__ Alo,
             const bf16* __restrict__ Bhi, const bf16* __restrict__ Blo,
             float* __restrict__ Cf, bf16* __restrict__ Chi, bf16* __restrict__ Clo,
             int M, int N, int K, int ldA, int ldB, int ldC,
             long sA, long sB, long sC, float alpha)
{
    extern __shared__ char smc[];
    const int bx = blockIdx.x, by = blockIdx.y, z = blockIdx.z;
    if (CSKIP && bx > by) return;   // tile fully above causal diagonal

    Ahi += (size_t)z * sA;  Alo += (size_t)z * sA;
    Bhi += (size_t)z * sB;  Blo += (size_t)z * sB;

    const int Keff = CK ? min(K, (by + 1) * 128) : K;
    const int nc = Keff >> 5;
    const int tid = threadIdx.x, wid = tid >> 5, lane = tid & 31;
    const int m0 = by * 128, n0 = bx * 128;
    const uint32_t smb = smem_u32(smc);

    // ---- load mapping: thread -> row tid, all 4 16B chunks of that row ----
    const int lrow = tid;
    const int lswz = (lrow >> 1) & 3;
    const uint32_t dRow = (uint32_t)(lrow * 64);
    uint32_t dq[4];
    #pragma unroll
    for (int q = 0; q < 4; q++) dq[q] = dRow + (uint32_t)((q ^ lswz) << 4);
    const bf16* gAh = Ahi + (size_t)(m0 + lrow) * ldA;
    const bf16* gAl = Alo + (size_t)(m0 + lrow) * ldA;
    const bf16* gBh = Bhi + (size_t)(n0 + lrow) * ldB;
    const bf16* gBl = Blo + (size_t)(n0 + lrow) * ldB;

#define PREFETCH(c, s) do { \
        uint32_t b_ = smb + (uint32_t)(s) * STAGEB; \
        const bf16* p_; \
        p_ = gAh + (size_t)(c) * 32; \
        CPA(b_ + dq[0], p_); CPA(b_ + dq[1], p_ + 8); \
        CPA(b_ + dq[2], p_ + 16); CPA(b_ + dq[3], p_ + 24); \
        p_ = gAl + (size_t)(c) * 32; \
        CPA(b_ + TILEB + dq[0], p_); CPA(b_ + TILEB + dq[1], p_ + 8); \
        CPA(b_ + TILEB + dq[2], p_ + 16); CPA(b_ + TILEB + dq[3], p_ + 24); \
        p_ = gBh + (size_t)(c) * 32; \
        CPA(b_ + 2 * TILEB + dq[0], p_); CPA(b_ + 2 * TILEB + dq[1], p_ + 8); \
        CPA(b_ + 2 * TILEB + dq[2], p_ + 16); CPA(b_ + 2 * TILEB + dq[3], p_ + 24); \
        p_ = gBl + (size_t)(c) * 32; \
        CPA(b_ + 3 * TILEB + dq[0], p_); CPA(b_ + 3 * TILEB + dq[1], p_ + 8); \
        CPA(b_ + 3 * TILEB + dq[2], p_ + 16); CPA(b_ + 3 * TILEB + dq[3], p_ + 24); \
        CP_COMMIT(); \
    } while (0)

    // ---- compute mapping: warp tile 64x64 (2m x 2n warps) ----
    const int wm = (wid & 1) * 64;
    const int wn = (wid >> 1) * 64;
    const int aRowL = lane & 15;
    const int aSwz = (aRowL >> 1) & 3;
    const int aCh = lane >> 4;
    const uint32_t aBase = (uint32_t)((wm + aRowL) * 64);
    const int bRowL = (lane & 7) + ((lane & 16) >> 1);
    const int bSwz = (bRowL >> 1) & 3;
    const int bCh = (lane & 8) >> 3;
    const uint32_t bBase = (uint32_t)((wn + bRowL) * 64);

    float acc[4][8][4];
    #pragma unroll
    for (int i = 0; i < 4; i++)
        #pragma unroll
        for (int j = 0; j < 8; j++)
            #pragma unroll
            for (int q = 0; q < 4; q++) acc[i][j][q] = 0.f;

    PREFETCH(0, 0);
    if (nc > 1) PREFETCH(1, 1);

    int st = 0;
    for (int c = 0; c < nc; ++c) {
        if (c + 1 < nc) CP_WAIT(1); else CP_WAIT(0);
        __syncthreads();
        if (c + 2 < nc) {
            int ps = st + 2; if (ps >= NSTAGE) ps -= NSTAGE;
            PREFETCH(c + 2, ps);
        }

        const uint32_t base = smb + (uint32_t)st * STAGEB;
        #pragma unroll
        for (int half = 0; half < 2; half++) {
            const uint32_t aCol = (uint32_t)(((half * 2 + aCh) ^ aSwz) << 4);
            const uint32_t bCol = (uint32_t)(((half * 2 + bCh) ^ bSwz) << 4);

            uint32_t ah[4][4];
            #pragma unroll
            for (int mi = 0; mi < 4; mi++)
                LDSM4(ah[mi], base + aBase + mi * 1024 + aCol);
            uint32_t bh[8][2];
            #pragma unroll
            for (int nb = 0; nb < 4; nb++) {
                uint32_t r4[4];
                LDSM4(r4, base + 2 * TILEB + bBase + nb * 1024 + bCol);
                bh[nb * 2][0] = r4[0]; bh[nb * 2][1] = r4[1];
                bh[nb * 2 + 1][0] = r4[2]; bh[nb * 2 + 1][1] = r4[3];
            }
            // issue bl loads, then P1 = ah*bh (32 independent MMAs)
            uint32_t bl[8][2];
            #pragma unroll
            for (int nb = 0; nb < 4; nb++) {
                uint32_t r4[4];
                LDSM4(r4, base + 3 * TILEB + bBase + nb * 1024 + bCol);
                bl[nb * 2][0] = r4[0]; bl[nb * 2][1] = r4[1];
                bl[nb * 2 + 1][0] = r4[2]; bl[nb * 2 + 1][1] = r4[3];
            }
            #pragma unroll
            for (int mi = 0; mi < 4; mi++)
                #pragma unroll
                for (int ni = 0; ni < 8; ni++)
                    MMA(acc[mi][ni], ah[mi], bh[ni]);

            // issue al loads, then P2 = ah*bl
            uint32_t al[4][4];
            #pragma unroll
            for (int mi = 0; mi < 4; mi++)
                LDSM4(al[mi], base + TILEB + aBase + mi * 1024 + aCol);
            #pragma unroll
            for (int mi = 0; mi < 4; mi++)
                #pragma unroll
                for (int ni = 0; ni < 8; ni++)
                    MMA(acc[mi][ni], ah[mi], bl[ni]);

            // P3 = al*bh
            #pragma unroll
            for (int mi = 0; mi < 4; mi++)
                #pragma unroll
                for (int ni = 0; ni < 8; ni++)
                    MMA(acc[mi][ni], al[mi], bh[ni]);
        }
        if (++st == NSTAGE) st = 0;
    }
#undef PREFETCH

    // ---- epilogue ----
    const int er = lane >> 2, ec = (lane & 3) * 2;
    if (EPI == 0) {
        float* Cz = Cf + (size_t)z * sC;
        #pragma unroll
        for (int mi = 0; mi < 4; mi++) {
            const int r1 = m0 + wm + mi * 16 + er;
            #pragma unroll
            for (int ni = 0; ni < 8; ni++) {
                const int c1 = n0 + wn + ni * 8 + ec;
                if (c1 < N) {
                    float2 v0 = make_float2(acc[mi][ni][0] * alpha, acc[mi][ni][1] * alpha);
                    float2 v1 = make_float2(acc[mi][ni][2] * alpha, acc[mi][ni][3] * alpha);
                    *(float2*)(Cz + (size_t)r1 * ldC + c1) = v0;
                    *(float2*)(Cz + (size_t)(r1 + 8) * ldC + c1) = v1;
                }
            }
        }
    } else {
        bf16* Ch = Chi + (size_t)z * sC;
        bf16* Cl = Clo + (size_t)z * sC;
        #pragma unroll
        for (int mi = 0; mi < 4; mi++) {
            const int r1 = m0 + wm + mi * 16 + er;
            #pragma unroll
            for (int ni = 0; ni < 8; ni++) {
                const int c1 = n0 + wn + ni * 8 + ec;
                if (c1 < N) {
                    bf16 h0, l0, h1, l1;
                    hlsplit(acc[mi][ni][0] * alpha, h0, l0);
                    hlsplit(acc[mi][ni][1] * alpha, h1, l1);
                    *(__nv_bfloat162*)(Ch + (size_t)r1 * ldC + c1) = __nv_bfloat162(h0, h1);
                    *(__nv_bfloat162*)(Cl + (size_t)r1 * ldC + c1) = __nv_bfloat162(l0, l1);
                    hlsplit(acc[mi][ni][2] * alpha, h0, l0);
                    hlsplit(acc[mi][ni][3] * alpha, h1, l1);
                    *(__nv_bfloat162*)(Ch + (size_t)(r1 + 8) * ldC + c1) = __nv_bfloat162(h0, h1);
                    *(__nv_bfloat162*)(Cl + (size_t)(r1 + 8) * ldC + c1) = __nv_bfloat162(l0, l1);
                }
            }
        }
    }
}

// ---------------- Launch ----------------
extern "C" void kernel_launch(void* const* d_in, const int* in_sizes, int n_in,
                              void* d_out, int out_size)
{
    (void)in_sizes; (void)n_in; (void)out_size;
    const float* x     = (const float*)d_in[0];
    const float* cosT  = (const float*)d_in[1];
    const float* sinT  = (const float*)d_in[2];
    const float* Wqkv  = (const float*)d_in[3];
    const float* Wqdec = (const float*)d_in[4];
    const float* Wout  = (const float*)d_in[5];
    float* out = (float*)d_out;

    float *lat, *qbuf, *scores;
    bf16 *xhi, *xlo, *wqkvThi, *wqkvTlo, *cqhi, *cqlo, *wqdecThi, *wqdecTlo;
    bf16 *qhi, *qlo, *khi, *klo, *vThi, *vTlo, *attnhi, *attnlo, *yhi, *ylo, *woutThi, *woutTlo;
    cudaGetSymbolAddress((void**)&lat, g_lat);
    cudaGetSymbolAddress((void**)&qbuf, g_qbuf);
    cudaGetSymbolAddress((void**)&scores, g_scores);
    cudaGetSymbolAddress((void**)&xhi, g_xhi);       cudaGetSymbolAddress((void**)&xlo, g_xlo);
    cudaGetSymbolAddress((void**)&wqkvThi, g_wqkvThi); cudaGetSymbolAddress((void**)&wqkvTlo, g_wqkvTlo);
    cudaGetSymbolAddress((void**)&cqhi, g_cqhi);     cudaGetSymbolAddress((void**)&cqlo, g_cqlo);
    cudaGetSymbolAddress((void**)&wqdecThi, g_wqdecThi); cudaGetSymbolAddress((void**)&wqdecTlo, g_wqdecTlo);
    cudaGetSymbolAddress((void**)&qhi, g_qhi);       cudaGetSymbolAddress((void**)&qlo, g_qlo);
    cudaGetSymbolAddress((void**)&khi, g_khi);       cudaGetSymbolAddress((void**)&klo, g_klo);
    cudaGetSymbolAddress((void**)&vThi, g_vThi);     cudaGetSymbolAddress((void**)&vTlo, g_vTlo);
    cudaGetSymbolAddress((void**)&attnhi, g_attnhi); cudaGetSymbolAddress((void**)&attnlo, g_attnlo);
    cudaGetSymbolAddress((void**)&yhi, g_yhi);       cudaGetSymbolAddress((void**)&ylo, g_ylo);
    cudaGetSymbolAddress((void**)&woutThi, g_woutThi); cudaGetSymbolAddress((void**)&woutTlo, g_woutTlo);

    cudaFuncSetAttribute((const void*)mmagemm<0, false, 0>,
                         cudaFuncAttributeMaxDynamicSharedMemorySize, SMEM_TOT);
    cudaFuncSetAttribute((const void*)mmagemm<1, false, 0>,
                         cudaFuncAttributeMaxDynamicSharedMemorySize, SMEM_TOT);
    cudaFuncSetAttribute((const void*)mmagemm<0, true, 1>,
                         cudaFuncAttributeMaxDynamicSharedMemorySize, SMEM_TOT);

    const float scale = 0.04419417382415922f;   // 1/sqrt(512)

    // 0-2: input conversions
    conv_x<<<8192, 256>>>(x, xhi, xlo);
    conv_wqkv<<<dim3(NPAD1 / 32, NEMBD / 32), 256>>>(Wqkv, wqkvThi, wqkvTlo);
    conv_w2<<<NQDBLK + NWOBLK, 256>>>(Wqdec, wqdecThi, wqdecTlo, Wout, woutThi, woutTlo);

    // 3: G1: lat = x @ Wqkv  [2048 x 1600]
    mmagemm<0, false, 0><<<dim3(13, 16, 1), 128, SMEM_TOT>>>(
        xhi, xlo, wqkvThi, wqkvTlo, lat, nullptr, nullptr,
        T_SEQ, LATD, NEMBD, NEMBD, NEMBD, LATD, 0, 0, 0, 1.f);

    // 4: conversions from lat (fused)
    conv_lat<<<NCQBLK + NVTBLK, 256>>>(lat, cqhi, cqlo, vThi, vTlo);

    // 5: G2: qbuf = c_q @ Wqdec  [2048 x 9216]
    mmagemm<0, false, 0><<<dim3(72, 16, 1), 128, SMEM_TOT>>>(
        cqhi, cqlo, wqdecThi, wqdecTlo, qbuf, nullptr, nullptr,
        T_SEQ, QTOT, QLOW, QLOW, QLOW, QTOT, 0, 0, 0, 1.f);

    // 6: RoPE + hi/lo q/k
    rope_pack_kernel<<<T_SEQ, 256>>>(lat, qbuf, cosT, sinT, khi, klo, qhi, qlo);

    // 7: scores[h] = scale * q_h @ k^T, causal tile skip
    mmagemm<1, false, 0><<<dim3(16, 16, NHEAD), 128, SMEM_TOT>>>(
        qhi, qlo, khi, klo, scores, nullptr, nullptr,
        T_SEQ, T_SEQ, QKHS, QTOT, QKHS, T_SEQ,
        (long)QKHS, 0, (long)T_SEQ * T_SEQ, scale);

    // 8: softmax -> hi/lo attn
    softmax_kernel<<<dim3(T_SEQ, NHEAD), 256>>>(scores, attnhi, attnlo);

    // 9: PV: y_h = attn_h @ v (K causal-truncated), bf16 hi/lo epilogue
    mmagemm<0, true, 1><<<dim3(4, 16, NHEAD), 128, SMEM_TOT>>>(
        attnhi, attnlo, vThi, vTlo, nullptr, yhi, ylo,
        T_SEQ, KVLOW, T_SEQ, T_SEQ, T_SEQ, YTOT,
        (long)T_SEQ * T_SEQ, 0, (long)KVLOW, 1.f);

    // 10: G3: out = y @ Wout  [2048 x 2048]
    mmagemm<0, false, 0><<<dim3(16, 16, 1), 128, SMEM_TOT>>>(
        yhi, ylo, woutThi, woutTlo, out, nullptr, nullptr,
        T_SEQ, NEMBD, YTOT, YTOT, YTOT, NEMBD, 0, 0, 0, 1.f);
}

// round 12
// speedup vs baseline: 1.8656x; 1.8656x over previous
#include <cuda_runtime.h>
#include <cuda_fp16.h>
#include <cstdint>

// ---------------- Problem constants ----------------
#define T_SEQ   2048
#define NEMBD   2048
#define NHEAD   16
#define KVLOW   512
#define QLOW    1024
#define ROPEHS  64
#define QKHS    576
#define LATD    1600
#define QTOT    9216
#define YTOT    8192
#define NPAD1   1664   // 1600 padded up to 13*128

typedef __half h16;

// ---------------- Scratch (device globals; no allocations allowed) ----------------
__device__ float g_lat[(size_t)T_SEQ * LATD];
__device__ float g_qbuf[(size_t)T_SEQ * QTOT];
__device__ float g_scores[(size_t)NHEAD * T_SEQ * T_SEQ];

__device__ h16 g_xh[(size_t)T_SEQ * NEMBD];
__device__ h16 g_wqkvThi[(size_t)NPAD1 * NEMBD];
__device__ h16 g_wqkvTlo[(size_t)NPAD1 * NEMBD];
__device__ h16 g_cqh[(size_t)T_SEQ * QLOW];
__device__ h16 g_wqdecThi[(size_t)QTOT * QLOW];
__device__ h16 g_wqdecTlo[(size_t)QTOT * QLOW];
__device__ h16 g_qh[(size_t)T_SEQ * QTOT];
__device__ h16 g_khi[(size_t)T_SEQ * QKHS];
__device__ h16 g_klo[(size_t)T_SEQ * QKHS];
__device__ h16 g_vThi[(size_t)KVLOW * T_SEQ];
__device__ h16 g_vTlo[(size_t)KVLOW * T_SEQ];
__device__ h16 g_attnh[(size_t)NHEAD * T_SEQ * T_SEQ];
__device__ h16 g_yh[(size_t)T_SEQ * YTOT];
__device__ h16 g_woutThi[(size_t)NEMBD * YTOT];
__device__ h16 g_woutTlo[(size_t)NEMBD * YTOT];

// ---------------- helpers ----------------
__device__ __forceinline__ void hsplit(float v, h16& h, h16& l) {
    h = __float2half_rn(v);
    l = __float2half_rn(v - __half2float(h));
}
__device__ __forceinline__ uint32_t smem_u32(const void* p) {
    uint32_t a;
    asm("{ .reg .u64 t; cvta.to.shared.u64 t, %1; cvt.u32.u64 %0, t; }" : "=r"(a) : "l"(p));
    return a;
}

#define CPA(dst, src) \
    asm volatile("cp.async.cg.shared.global [%0], [%1], 16;\n" :: "r"(dst), "l"(src))
#define CP_COMMIT() asm volatile("cp.async.commit_group;\n" ::: "memory")
#define CP_WAIT(N)  asm volatile("cp.async.wait_group %0;\n" :: "n"(N) : "memory")

#define LDSM4(r, addr) \
    asm volatile("ldmatrix.sync.aligned.m8n8.x4.shared.b16 {%0,%1,%2,%3}, [%4];" \
        : "=r"((r)[0]), "=r"((r)[1]), "=r"((r)[2]), "=r"((r)[3]) : "r"(addr))

#define MMA(d, a, b) \
    asm volatile("mma.sync.aligned.m16n8k16.row.col.f32.f16.f16.f32 " \
        "{%0,%1,%2,%3}, {%4,%5,%6,%7}, {%8,%9}, {%0,%1,%2,%3};" \
        : "+f"((d)[0]), "+f"((d)[1]), "+f"((d)[2]), "+f"((d)[3]) \
        : "r"((a)[0]), "r"((a)[1]), "r"((a)[2]), "r"((a)[3]), "r"((b)[0]), "r"((b)[1]))

// ---------------- Conversion bodies ----------------
// f32 [R][C] (row stride ldin) -> single fp16 [R][C]
__device__ __forceinline__ void conv1_body(const float* __restrict__ in,
                                           h16* __restrict__ out,
                                           int R, int C, int ldin, size_t idx)
{
    int half = C >> 1;
    if (idx >= (size_t)R * half) return;
    int r = (int)(idx / half);
    int c = (int)(idx - (size_t)r * half) * 2;
    float v0 = in[(size_t)r * ldin + c];
    float v1 = in[(size_t)r * ldin + c + 1];
    *(__half2*)(out + (size_t)r * C + c) = __floats2half2_rn(v0, v1);
}

// f32 [R][C] (row stride ldin) -> transposed hi/lo fp16 [Cpad][R]; rows c>=C zero.
__device__ __forceinline__ void cvT2_body(const float* __restrict__ in,
                                          h16* __restrict__ hi, h16* __restrict__ lo,
                                          int R, int C, int ldin, int bx, int by,
                                          int tid, float (*ts)[33])
{
    const int c0 = bx * 32, r0 = by * 32;
    const int j = tid & 31;
    #pragma unroll
    for (int q = 0; q < 4; q++) {
        int i = (tid >> 5) + q * 8;
        ts[j][i] = (c0 + j < C) ? in[(size_t)(r0 + i) * ldin + (c0 + j)] : 0.f;
    }
    __syncthreads();
    const int cl = tid >> 3, g = tid & 7;
    h16 h[4], l[4];
    #pragma unroll
    for (int q = 0; q < 4; q++) hsplit(ts[cl][g * 4 + q], h[q], l[q]);
    size_t base = (size_t)(c0 + cl) * R + r0 + g * 4;
    *(__half2*)(hi + base)     = __half2(h[0], h[1]);
    *(__half2*)(hi + base + 2) = __half2(h[2], h[3]);
    *(__half2*)(lo + base)     = __half2(l[0], l[1]);
    *(__half2*)(lo + base + 2) = __half2(l[2], l[3]);
}

// launch 0: x -> single fp16
__global__ void conv_x(const float* __restrict__ x, h16* __restrict__ out)
{
    conv1_body(x, out, T_SEQ, NEMBD, NEMBD, (size_t)blockIdx.x * 256 + threadIdx.x);
}
// launch 1: WqkvT hi/lo
__global__ void conv_wqkv(const float* __restrict__ w, h16* __restrict__ hi, h16* __restrict__ lo)
{
    __shared__ float ts[32][33];
    cvT2_body(w, hi, lo, NEMBD, LATD, LATD, blockIdx.x, blockIdx.y, threadIdx.x, ts);
}
// launch 2: fused WqdecT + WoutT (hi/lo)
#define NQDBLK ((QTOT / 32) * (QLOW / 32))      // 9216
#define NWOBLK ((NEMBD / 32) * (YTOT / 32))     // 16384
__global__ void conv_w2(const float* __restrict__ wqdec, h16* __restrict__ qdhi, h16* __restrict__ qdlo,
                        const float* __restrict__ wout, h16* __restrict__ wohi, h16* __restrict__ wolo)
{
    __shared__ float ts[32][33];
    int b = blockIdx.x;
    if (b < NQDBLK) {
        cvT2_body(wqdec, qdhi, qdlo, QLOW, QTOT, QTOT, b % (QTOT / 32), b / (QTOT / 32), threadIdx.x, ts);
    } else {
        b -= NQDBLK;
        cvT2_body(wout, wohi, wolo, YTOT, NEMBD, NEMBD, b % (NEMBD / 32), b / (NEMBD / 32), threadIdx.x, ts);
    }
}
// launch 4: fused cq (single) + vT (hi/lo transpose)
#define NCQBLK 4096                              // 2048*1024/2/256
#define NVTBLK ((KVLOW / 32) * (T_SEQ / 32))     // 1024
__global__ void conv_lat(const float* __restrict__ lat,
                         h16* __restrict__ cqh,
                         h16* __restrict__ vthi, h16* __restrict__ vtlo)
{
    __shared__ float ts[32][33];
    int b = blockIdx.x;
    if (b < NCQBLK) {
        conv1_body(lat + (KVLOW + ROPEHS), cqh, T_SEQ, QLOW, LATD,
                   (size_t)b * 256 + threadIdx.x);
    } else {
        b -= NCQBLK;
        cvT2_body(lat, vthi, vtlo, T_SEQ, KVLOW, LATD, b % (KVLOW / 32), b / (KVLOW / 32),
                  threadIdx.x, ts);
    }
}

// ---------------- RoPE: k -> hi/lo fp16, q -> single fp16 ----------------
__global__ void rope_pack_kernel(const float* __restrict__ lat, const float* __restrict__ qbuf,
                                 const float* __restrict__ cosT, const float* __restrict__ sinT,
                                 h16* __restrict__ khi, h16* __restrict__ klo,
                                 h16* __restrict__ qh)
{
    const int t = blockIdx.x, tid = threadIdx.x;
    __shared__ float cs[ROPEHS], sn[ROPEHS];
    if (tid < ROPEHS) {
        cs[tid] = cosT[(size_t)t * ROPEHS + tid];
        sn[tid] = sinT[(size_t)t * ROPEHS + tid];
    }
    __syncthreads();

    const float* lrow = lat + (size_t)t * LATD;
    h16* krh = khi + (size_t)t * QKHS;
    h16* krl = klo + (size_t)t * QKHS;
    for (int p = tid; p < QKHS / 2; p += 256) {
        int e = p * 2;
        float v[2];
        #pragma unroll
        for (int u = 0; u < 2; u++) {
            int ee = e + u;
            if (ee < KVLOW) v[u] = lrow[ee];
            else {
                int i2 = ee - KVLOW;
                float xv = lrow[ee];
                v[u] = (i2 < 32) ? xv * cs[i2] - lrow[ee + 32] * sn[i2]
                                 : xv * cs[i2] + lrow[ee - 32] * sn[i2];
            }
        }
        h16 h0, l0, h1, l1;
        hsplit(v[0], h0, l0); hsplit(v[1], h1, l1);
        *(__half2*)(krh + e) = __half2(h0, h1);
        *(__half2*)(krl + e) = __half2(l0, l1);
    }

    const float* qrow = qbuf + (size_t)t * QTOT;
    h16* qrh = qh + (size_t)t * QTOT;
    for (int p = tid; p < QTOT / 2; p += 256) {
        int e = p * 2;
        float v[2];
        #pragma unroll
        for (int u = 0; u < 2; u++) {
            int ee = e + u;
            int hh = ee / QKHS;
            int i = ee - hh * QKHS;
            if (i < KVLOW) v[u] = qrow[ee];
            else {
                int i2 = i - KVLOW;
                float xv = qrow[ee];
                v[u] = (i2 < 32) ? xv * cs[i2] - qrow[ee + 32] * sn[i2]
                                 : xv * cs[i2] + qrow[ee - 32] * sn[i2];
            }
        }
        *(__half2*)(qrh + e) = __floats2half2_rn(v[0], v[1]);
    }
}

// ---------------- Softmax -> single fp16 attn (zero-filled to 128-boundary) ----------------
__global__ __launch_bounds__(256)
void softmax_kernel(const float* __restrict__ scores, h16* __restrict__ attn)
{
    __shared__ float srow[T_SEQ];
    __shared__ float red[8];
    const int t = blockIdx.x, h = blockIdx.y, tid = threadIdx.x;
    const float* row = scores + ((size_t)h * T_SEQ + t) * T_SEQ;
    const int n = t + 1;

    float m = -3.4e38f;
    for (int s = tid; s < n; s += 256) { float v = row[s]; srow[s] = v; m = fmaxf(m, v); }
    #pragma unroll
    for (int o = 16; o; o >>= 1) m = fmaxf(m, __shfl_xor_sync(0xffffffffu, m, o));
    if ((tid & 31) == 0) red[tid >> 5] = m;
    __syncthreads();
    float mmax = red[0];
    #pragma unroll
    for (int i = 1; i < 8; i++) mmax = fmaxf(mmax, red[i]);
    __syncthreads();

    float sum = 0.f;
    for (int s = tid; s < n; s += 256) { float e = __expf(srow[s] - mmax); srow[s] = e; sum += e; }
    #pragma unroll
    for (int o = 16; o; o >>= 1) sum += __shfl_xor_sync(0xffffffffu, sum, o);
    if ((tid & 31) == 0) red[tid >> 5] = sum;
    __syncthreads();
    float total = 0.f;
    #pragma unroll
    for (int i = 0; i < 8; i++) total += red[i];
    const float inv = 1.f / total;

    h16* arow = attn + ((size_t)h * T_SEQ + t) * T_SEQ;
    const int kpad = ((t >> 7) + 1) << 7;   // 128-granular for PV K truncation
    for (int p = tid; p < (kpad >> 1); p += 256) {
        int s0 = 2 * p;
        float v0 = (s0 <= t) ? srow[s0] * inv : 0.f;
        float v1 = (s0 + 1 <= t) ? srow[s0 + 1] * inv : 0.f;
        *(__half2*)(arow + s0) = __floats2half2_rn(v0, v1);
    }
}

// ---------------- mma.sync GEMM: C = alpha * A * (Bhi+Blo)^T ----------------
// fp16 2-product scheme: A single fp16 (rounding ~2^-12), B split hi/lo (exact).
// CTA tile 128x128, 256 threads (8 warps, 2m x 4n of 64x32), BK=32,
// 4-stage smem pipeline, compact XOR-swizzled smem, 1 sync/chunk, 2 CTAs/SM.
#define TILEB  8192                 // 128 rows x 64B
#define STAGEB (3 * TILEB)          // 24576: A, Bhi, Blo
#define NSTAGE 4
#define SMEM_TOT (NSTAGE * STAGEB)  // 98304

template<int CSKIP, bool CK, int EPI>   // EPI: 0 -> f32 C, 1 -> single fp16 C
__global__ __launch_bounds__(256, 2)
void mmagemm(const h16* __restrict__ A, const h16* __restrict__ Bhi, const h16* __restrict__ Blo,
             float* __restrict__ Cf, h16* __restrict__ Ch,
             int M, int N, int K, int ldA, int ldB, int ldC,
             long sA, long sB, long sC, float alpha)
{
    extern __shared__ char smc[];
    const int bx = blockIdx.x, by = blockIdx.y, z = blockIdx.z;
    if (CSKIP && bx > by) return;   // tile fully above causal diagonal

    A += (size_t)z * sA;
    Bhi += (size_t)z * sB;  Blo += (size_t)z * sB;

    const int Keff = CK ? min(K, (by + 1) * 128) : K;
    const int nc = Keff >> 5;
    const int tid = threadIdx.x, wid = tid >> 5, lane = tid & 31;
    const int m0 = by * 128, n0 = bx * 128;
    const uint32_t smb = smem_u32(smc);

    // ---- load mapping: thread -> row tid>>1, chunks {(tid&1)*2, (tid&1)*2+1} ----
    const int lrow = tid >> 1;
    const int lc0  = (tid & 1) * 2;
    const int lswz = (lrow >> 1) & 3;
    const uint32_t dRow = (uint32_t)(lrow * 64);
    const uint32_t d0 = dRow + (uint32_t)((lc0 ^ lswz) << 4);
    const uint32_t d1 = dRow + (uint32_t)(((lc0 + 1) ^ lswz) << 4);
    const h16* gA  = A   + (size_t)(m0 + lrow) * ldA + lc0 * 8;
    const h16* gBh = Bhi + (size_t)(n0 + lrow) * ldB + lc0 * 8;
    const h16* gBl = Blo + (size_t)(n0 + lrow) * ldB + lc0 * 8;

#define PREFETCH(c, s) do { \
        uint32_t b_ = smb + (uint32_t)(s) * STAGEB; \
        const h16* p_ = gA + (size_t)(c) * 32; \
        CPA(b_ + d0, p_); CPA(b_ + d1, p_ + 8); \
        p_ = gBh + (size_t)(c) * 32; \
        CPA(b_ + TILEB + d0, p_); CPA(b_ + TILEB + d1, p_ + 8); \
        p_ = gBl + (size_t)(c) * 32; \
        CPA(b_ + 2 * TILEB + d0, p_); CPA(b_ + 2 * TILEB + d1, p_ + 8); \
        CP_COMMIT(); \
    } while (0)

    // ---- compute mapping: warp tile 64x32 (2m x 4n warps) ----
    const int wm = (wid & 1) * 64;
    const int wn = (wid >> 1) * 32;
    const int aRowL = lane & 15;
    const int aSwz = (aRowL >> 1) & 3;
    const int aCh = lane >> 4;
    const uint32_t aBase = (uint32_t)((wm + aRowL) * 64);
    const int bRowL = (lane & 7) + ((lane & 16) >> 1);
    const int bSwz = (bRowL >> 1) & 3;
    const int bCh = (lane & 8) >> 3;
    const uint32_t bBase = (uint32_t)((wn + bRowL) * 64);

    float acc[4][4][4];
    #pragma unroll
    for (int i = 0; i < 4; i++)
        #pragma unroll
        for (int j = 0; j < 4; j++)
            #pragma unroll
            for (int q = 0; q < 4; q++) acc[i][j][q] = 0.f;

    PREFETCH(0, 0);
    if (nc > 1) PREFETCH(1, 1);
    if (nc > 2) PREFETCH(2, 2);

    int st = 0;
    for (int c = 0; c < nc; ++c) {
        const int rem = nc - 1 - c;
        if (rem >= 2)      CP_WAIT(2);
        else if (rem == 1) CP_WAIT(1);
        else               CP_WAIT(0);
        __syncthreads();
        if (c + 3 < nc) {
            int ps = st + 3; if (ps >= NSTAGE) ps -= NSTAGE;
            PREFETCH(c + 3, ps);
        }

        const uint32_t base = smb + (uint32_t)st * STAGEB;
        #pragma unroll
        for (int half = 0; half < 2; half++) {
            const uint32_t aCol = (uint32_t)(((half * 2 + aCh) ^ aSwz) << 4);
            const uint32_t bCol = (uint32_t)(((half * 2 + bCh) ^ bSwz) << 4);

            uint32_t ah[4][4];
            #pragma unroll
            for (int mi = 0; mi < 4; mi++)
                LDSM4(ah[mi], base + aBase + mi * 1024 + aCol);
            uint32_t bh[4][2];
            #pragma unroll
            for (int nb = 0; nb < 2; nb++) {
                uint32_t r4[4];
                LDSM4(r4, base + TILEB + bBase + nb * 1024 + bCol);
                bh[nb * 2][0] = r4[0]; bh[nb * 2][1] = r4[1];
                bh[nb * 2 + 1][0] = r4[2]; bh[nb * 2 + 1][1] = r4[3];
            }
            // issue Blo loads, then P1 = A*Bh (16 independent MMAs)
            uint32_t bl[4][2];
            #pragma unroll
            for (int nb = 0; nb < 2; nb++) {
                uint32_t r4[4];
                LDSM4(r4, base + 2 * TILEB + bBase + nb * 1024 + bCol);
                bl[nb * 2][0] = r4[0]; bl[nb * 2][1] = r4[1];
                bl[nb * 2 + 1][0] = r4[2]; bl[nb * 2 + 1][1] = r4[3];
            }
            #pragma unroll
            for (int mi = 0; mi < 4; mi++)
                #pragma unroll
                for (int ni = 0; ni < 4; ni++)
                    MMA(acc[mi][ni], ah[mi], bh[ni]);
            // P2 = A*Bl
            #pragma unroll
            for (int mi = 0; mi < 4; mi++)
                #pragma unroll
                for (int ni = 0; ni < 4; ni++)
                    MMA(acc[mi][ni], ah[mi], bl[ni]);
        }
        if (++st == NSTAGE) st = 0;
    }
#undef PREFETCH

    // ---- epilogue ----
    const int er = lane >> 2, ec = (lane & 3) * 2;
    if (EPI == 0) {
        float* Cz = Cf + (size_t)z * sC;
        #pragma unroll
        for (int mi = 0; mi < 4; mi++) {
            const int r1 = m0 + wm + mi * 16 + er;
            #pragma unroll
            for (int ni = 0; ni < 4; ni++) {
                const int c1 = n0 + wn + ni * 8 + ec;
                if (c1 < N) {
                    float2 v0 = make_float2(acc[mi][ni][0] * alpha, acc[mi][ni][1] * alpha);
                    float2 v1 = make_float2(acc[mi][ni][2] * alpha, acc[mi][ni][3] * alpha);
                    *(float2*)(Cz + (size_t)r1 * ldC + c1) = v0;
                    *(float2*)(Cz + (size_t)(r1 + 8) * ldC + c1) = v1;
                }
            }
        }
    } else {
        h16* Cz = Ch + (size_t)z * sC;
        #pragma unroll
        for (int mi = 0; mi < 4; mi++) {
            const int r1 = m0 + wm + mi * 16 + er;
            #pragma unroll
            for (int ni = 0; ni < 4; ni++) {
                const int c1 = n0 + wn + ni * 8 + ec;
                if (c1 < N) {
                    *(__half2*)(Cz + (size_t)r1 * ldC + c1) =
                        __floats2half2_rn(acc[mi][ni][0] * alpha, acc[mi][ni][1] * alpha);
                    *(__half2*)(Cz + (size_t)(r1 + 8) * ldC + c1) =
                        __floats2half2_rn(acc[mi][ni][2] * alpha, acc[mi][ni][3] * alpha);
                }
            }
        }
    }
}

// ---------------- Launch ----------------
extern "C" void kernel_launch(void* const* d_in, const int* in_sizes, int n_in,
                              void* d_out, int out_size)
{
    (void)in_sizes; (void)n_in; (void)out_size;
    const float* x     = (const float*)d_in[0];
    const float* cosT  = (const float*)d_in[1];
    const float* sinT  = (const float*)d_in[2];
    const float* Wqkv  = (const float*)d_in[3];
    const float* Wqdec = (const float*)d_in[4];
    const float* Wout  = (const float*)d_in[5];
    float* out = (float*)d_out;

    float *lat, *qbuf, *scores;
    h16 *xh, *wqkvThi, *wqkvTlo, *cqh, *wqdecThi, *wqdecTlo;
    h16 *qh, *khi, *klo, *vThi, *vTlo, *attnh, *yh, *woutThi, *woutTlo;
    cudaGetSymbolAddress((void**)&lat, g_lat);
    cudaGetSymbolAddress((void**)&qbuf, g_qbuf);
    cudaGetSymbolAddress((void**)&scores, g_scores);
    cudaGetSymbolAddress((void**)&xh, g_xh);
    cudaGetSymbolAddress((void**)&wqkvThi, g_wqkvThi); cudaGetSymbolAddress((void**)&wqkvTlo, g_wqkvTlo);
    cudaGetSymbolAddress((void**)&cqh, g_cqh);
    cudaGetSymbolAddress((void**)&wqdecThi, g_wqdecThi); cudaGetSymbolAddress((void**)&wqdecTlo, g_wqdecTlo);
    cudaGetSymbolAddress((void**)&qh, g_qh);
    cudaGetSymbolAddress((void**)&khi, g_khi);       cudaGetSymbolAddress((void**)&klo, g_klo);
    cudaGetSymbolAddress((void**)&vThi, g_vThi);     cudaGetSymbolAddress((void**)&vTlo, g_vTlo);
    cudaGetSymbolAddress((void**)&attnh, g_attnh);
    cudaGetSymbolAddress((void**)&yh, g_yh);
    cudaGetSymbolAddress((void**)&woutThi, g_woutThi); cudaGetSymbolAddress((void**)&woutTlo, g_woutTlo);

    cudaFuncSetAttribute((const void*)mmagemm<0, false, 0>,
                         cudaFuncAttributeMaxDynamicSharedMemorySize, SMEM_TOT);
    cudaFuncSetAttribute((const void*)mmagemm<1, false, 0>,
                         cudaFuncAttributeMaxDynamicSharedMemorySize, SMEM_TOT);
    cudaFuncSetAttribute((const void*)mmagemm<0, true, 1>,
                         cudaFuncAttributeMaxDynamicSharedMemorySize, SMEM_TOT);

    const float scale = 0.04419417382415922f;   // 1/sqrt(512)

    // 0-2: input conversions
    conv_x<<<8192, 256>>>(x, xh);
    conv_wqkv<<<dim3(NPAD1 / 32, NEMBD / 32), 256>>>(Wqkv, wqkvThi, wqkvTlo);
    conv_w2<<<NQDBLK + NWOBLK, 256>>>(Wqdec, wqdecThi, wqdecTlo, Wout, woutThi, woutTlo);

    // 3: G1: lat = x @ Wqkv  [2048 x 1600]
    mmagemm<0, false, 0><<<dim3(13, 16, 1), 256, SMEM_TOT>>>(
        xh, wqkvThi, wqkvTlo, lat, nullptr,
        T_SEQ, LATD, NEMBD, NEMBD, NEMBD, LATD, 0, 0, 0, 1.f);

    // 4: conversions from lat (fused)
    conv_lat<<<NCQBLK + NVTBLK, 256>>>(lat, cqh, vThi, vTlo);

    // 5: G2: qbuf = c_q @ Wqdec  [2048 x 9216]
    mmagemm<0, false, 0><<<dim3(72, 16, 1), 256, SMEM_TOT>>>(
        cqh, wqdecThi, wqdecTlo, qbuf, nullptr,
        T_SEQ, QTOT, QLOW, QLOW, QLOW, QTOT, 0, 0, 0, 1.f);

    // 6: RoPE: k hi/lo, q single
    rope_pack_kernel<<<T_SEQ, 256>>>(lat, qbuf, cosT, sinT, khi, klo, qh);

    // 7: scores[h] = scale * q_h @ k^T, causal tile skip
    mmagemm<1, false, 0><<<dim3(16, 16, NHEAD), 256, SMEM_TOT>>>(
        qh, khi, klo, scores, nullptr,
        T_SEQ, T_SEQ, QKHS, QTOT, QKHS, T_SEQ,
        (long)QKHS, 0, (long)T_SEQ * T_SEQ, scale);

    // 8: softmax -> single fp16 attn
    softmax_kernel<<<dim3(T_SEQ, NHEAD), 256>>>(scores, attnh);

    // 9: PV: y_h = attn_h @ v (K causal-truncated), fp16 epilogue
    mmagemm<0, true, 1><<<dim3(4, 16, NHEAD), 256, SMEM_TOT>>>(
        attnh, vThi, vTlo, nullptr, yh,
        T_SEQ, KVLOW, T_SEQ, T_SEQ, T_SEQ, YTOT,
        (long)T_SEQ * T_SEQ, 0, (long)KVLOW, 1.f);

    // 10: G3: out = y @ Wout  [2048 x 2048]
    mmagemm<0, false, 0><<<dim3(16, 16, 1), 256, SMEM_TOT>>>(
        yh, woutThi, woutTlo, out, nullptr,
        T_SEQ, NEMBD, YTOT, YTOT, YTOT, NEMBD, 0, 0, 0, 1.f);
}

// round 13
// speedup vs baseline: 2.8995x; 1.5542x over previous
#include <cuda_runtime.h>
#include <cuda_fp16.h>
#include <cstdint>

// ---------------- Problem constants ----------------
#define T_SEQ   2048
#define NEMBD   2048
#define NHEAD   16
#define KVLOW   512
#define QLOW    1024
#define ROPEHS  64
#define QKHS    576
#define LATD    1600
#define QTOT    9216
#define YTOT    8192
#define NPAD1   1664   // 1600 padded up to 13*128

typedef __half h16;

// ---------------- Scratch (device globals; no allocations allowed) ----------------
__device__ float g_lat[(size_t)T_SEQ * LATD];
__device__ float g_qbuf[(size_t)T_SEQ * QTOT];
__device__ float g_scores[(size_t)NHEAD * T_SEQ * T_SEQ];

__device__ h16 g_xh[(size_t)T_SEQ * NEMBD];
__device__ h16 g_wqkvT[(size_t)NPAD1 * NEMBD];
__device__ h16 g_cqh[(size_t)T_SEQ * QLOW];
__device__ h16 g_wqdecT[(size_t)QTOT * QLOW];
__device__ h16 g_qh[(size_t)T_SEQ * QTOT];
__device__ h16 g_kh[(size_t)T_SEQ * QKHS];
__device__ h16 g_vT[(size_t)KVLOW * T_SEQ];
__device__ h16 g_attnh[(size_t)NHEAD * T_SEQ * T_SEQ];
__device__ h16 g_yh[(size_t)T_SEQ * YTOT];
__device__ h16 g_woutT[(size_t)NEMBD * YTOT];

// ---------------- helpers ----------------
__device__ __forceinline__ uint32_t smem_u32(const void* p) {
    uint32_t a;
    asm("{ .reg .u64 t; cvta.to.shared.u64 t, %1; cvt.u32.u64 %0, t; }" : "=r"(a) : "l"(p));
    return a;
}

#define CPA(dst, src) \
    asm volatile("cp.async.cg.shared.global [%0], [%1], 16;\n" :: "r"(dst), "l"(src))
#define CP_COMMIT() asm volatile("cp.async.commit_group;\n" ::: "memory")
#define CP_WAIT(N)  asm volatile("cp.async.wait_group %0;\n" :: "n"(N) : "memory")

#define LDSM4(r, addr) \
    asm volatile("ldmatrix.sync.aligned.m8n8.x4.shared.b16 {%0,%1,%2,%3}, [%4];" \
        : "=r"((r)[0]), "=r"((r)[1]), "=r"((r)[2]), "=r"((r)[3]) : "r"(addr))

#define MMA(d, a, b) \
    asm volatile("mma.sync.aligned.m16n8k16.row.col.f32.f16.f16.f32 " \
        "{%0,%1,%2,%3}, {%4,%5,%6,%7}, {%8,%9}, {%0,%1,%2,%3};" \
        : "+f"((d)[0]), "+f"((d)[1]), "+f"((d)[2]), "+f"((d)[3]) \
        : "r"((a)[0]), "r"((a)[1]), "r"((a)[2]), "r"((a)[3]), "r"((b)[0]), "r"((b)[1]))

// ---------------- Conversion bodies ----------------
// f32 [R][C] (row stride ldin) -> single fp16 [R][C]
__device__ __forceinline__ void conv1_body(const float* __restrict__ in,
                                           h16* __restrict__ out,
                                           int R, int C, int ldin, size_t idx)
{
    int half = C >> 1;
    if (idx >= (size_t)R * half) return;
    int r = (int)(idx / half);
    int c = (int)(idx - (size_t)r * half) * 2;
    float v0 = in[(size_t)r * ldin + c];
    float v1 = in[(size_t)r * ldin + c + 1];
    *(__half2*)(out + (size_t)r * C + c) = __floats2half2_rn(v0, v1);
}

// f32 [R][C] (row stride ldin) -> transposed single fp16 [Cpad][R]; rows c>=C zero.
__device__ __forceinline__ void cvT1_body(const float* __restrict__ in,
                                          h16* __restrict__ out,
                                          int R, int C, int ldin, int bx, int by,
                                          int tid, float (*ts)[33])
{
    const int c0 = bx * 32, r0 = by * 32;
    const int j = tid & 31;
    #pragma unroll
    for (int q = 0; q < 4; q++) {
        int i = (tid >> 5) + q * 8;
        ts[j][i] = (c0 + j < C) ? in[(size_t)(r0 + i) * ldin + (c0 + j)] : 0.f;
    }
    __syncthreads();
    const int cl = tid >> 3, g = tid & 7;
    size_t base = (size_t)(c0 + cl) * R + r0 + g * 4;
    *(__half2*)(out + base)     = __floats2half2_rn(ts[cl][g * 4 + 0], ts[cl][g * 4 + 1]);
    *(__half2*)(out + base + 2) = __floats2half2_rn(ts[cl][g * 4 + 2], ts[cl][g * 4 + 3]);
}

// launch 0: x -> single fp16
__global__ void conv_x(const float* __restrict__ x, h16* __restrict__ out)
{
    conv1_body(x, out, T_SEQ, NEMBD, NEMBD, (size_t)blockIdx.x * 256 + threadIdx.x);
}
// launch 1: WqkvT
__global__ void conv_wqkv(const float* __restrict__ w, h16* __restrict__ out)
{
    __shared__ float ts[32][33];
    cvT1_body(w, out, NEMBD, LATD, LATD, blockIdx.x, blockIdx.y, threadIdx.x, ts);
}
// launch 2: fused WqdecT + WoutT
#define NQDBLK ((QTOT / 32) * (QLOW / 32))      // 9216
#define NWOBLK ((NEMBD / 32) * (YTOT / 32))     // 16384
__global__ void conv_w2(const float* __restrict__ wqdec, h16* __restrict__ qd,
                        const float* __restrict__ wout, h16* __restrict__ wo)
{
    __shared__ float ts[32][33];
    int b = blockIdx.x;
    if (b < NQDBLK) {
        cvT1_body(wqdec, qd, QLOW, QTOT, QTOT, b % (QTOT / 32), b / (QTOT / 32), threadIdx.x, ts);
    } else {
        b -= NQDBLK;
        cvT1_body(wout, wo, YTOT, NEMBD, NEMBD, b % (NEMBD / 32), b / (NEMBD / 32), threadIdx.x, ts);
    }
}
// launch 4: fused cq (single) + vT (single transpose)
#define NCQBLK 4096                              // 2048*1024/2/256
#define NVTBLK ((KVLOW / 32) * (T_SEQ / 32))     // 1024
__global__ void conv_lat(const float* __restrict__ lat,
                         h16* __restrict__ cqh, h16* __restrict__ vt)
{
    __shared__ float ts[32][33];
    int b = blockIdx.x;
    if (b < NCQBLK) {
        conv1_body(lat + (KVLOW + ROPEHS), cqh, T_SEQ, QLOW, LATD,
                   (size_t)b * 256 + threadIdx.x);
    } else {
        b -= NCQBLK;
        cvT1_body(lat, vt, T_SEQ, KVLOW, LATD, b % (KVLOW / 32), b / (KVLOW / 32),
                  threadIdx.x, ts);
    }
}

// ---------------- RoPE: k -> single fp16, q -> single fp16 ----------------
__global__ void rope_pack_kernel(const float* __restrict__ lat, const float* __restrict__ qbuf,
                                 const float* __restrict__ cosT, const float* __restrict__ sinT,
                                 h16* __restrict__ kh, h16* __restrict__ qh)
{
    const int t = blockIdx.x, tid = threadIdx.x;
    __shared__ float cs[ROPEHS], sn[ROPEHS];
    if (tid < ROPEHS) {
        cs[tid] = cosT[(size_t)t * ROPEHS + tid];
        sn[tid] = sinT[(size_t)t * ROPEHS + tid];
    }
    __syncthreads();

    const float* lrow = lat + (size_t)t * LATD;
    h16* krow = kh + (size_t)t * QKHS;
    for (int p = tid; p < QKHS / 2; p += 256) {
        int e = p * 2;
        float v[2];
        #pragma unroll
        for (int u = 0; u < 2; u++) {
            int ee = e + u;
            if (ee < KVLOW) v[u] = lrow[ee];
            else {
                int i2 = ee - KVLOW;
                float xv = lrow[ee];
                v[u] = (i2 < 32) ? xv * cs[i2] - lrow[ee + 32] * sn[i2]
                                 : xv * cs[i2] + lrow[ee - 32] * sn[i2];
            }
        }
        *(__half2*)(krow + e) = __floats2half2_rn(v[0], v[1]);
    }

    const float* qrow = qbuf + (size_t)t * QTOT;
    h16* qrh = qh + (size_t)t * QTOT;
    for (int p = tid; p < QTOT / 2; p += 256) {
        int e = p * 2;
        float v[2];
        #pragma unroll
        for (int u = 0; u < 2; u++) {
            int ee = e + u;
            int hh = ee / QKHS;
            int i = ee - hh * QKHS;
            if (i < KVLOW) v[u] = qrow[ee];
            else {
                int i2 = i - KVLOW;
                float xv = qrow[ee];
                v[u] = (i2 < 32) ? xv * cs[i2] - qrow[ee + 32] * sn[i2]
                                 : xv * cs[i2] + qrow[ee - 32] * sn[i2];
            }
        }
        *(__half2*)(qrh + e) = __floats2half2_rn(v[0], v[1]);
    }
}

// ---------------- Softmax -> single fp16 attn (zero-filled to 128-boundary) ----------------
__global__ __launch_bounds__(256)
void softmax_kernel(const float* __restrict__ scores, h16* __restrict__ attn)
{
    __shared__ float srow[T_SEQ];
    __shared__ float red[8];
    const int t = blockIdx.x, h = blockIdx.y, tid = threadIdx.x;
    const float* row = scores + ((size_t)h * T_SEQ + t) * T_SEQ;
    const int n = t + 1;

    float m = -3.4e38f;
    for (int s = tid; s < n; s += 256) { float v = row[s]; srow[s] = v; m = fmaxf(m, v); }
    #pragma unroll
    for (int o = 16; o; o >>= 1) m = fmaxf(m, __shfl_xor_sync(0xffffffffu, m, o));
    if ((tid & 31) == 0) red[tid >> 5] = m;
    __syncthreads();
    float mmax = red[0];
    #pragma unroll
    for (int i = 1; i < 8; i++) mmax = fmaxf(mmax, red[i]);
    __syncthreads();

    float sum = 0.f;
    for (int s = tid; s < n; s += 256) { float e = __expf(srow[s] - mmax); srow[s] = e; sum += e; }
    #pragma unroll
    for (int o = 16; o; o >>= 1) sum += __shfl_xor_sync(0xffffffffu, sum, o);
    if ((tid & 31) == 0) red[tid >> 5] = sum;
    __syncthreads();
    float total = 0.f;
    #pragma unroll
    for (int i = 0; i < 8; i++) total += red[i];
    const float inv = 1.f / total;

    h16* arow = attn + ((size_t)h * T_SEQ + t) * T_SEQ;
    const int kpad = ((t >> 7) + 1) << 7;   // 128-granular for PV K truncation
    for (int p = tid; p < (kpad >> 1); p += 256) {
        int s0 = 2 * p;
        float v0 = (s0 <= t) ? srow[s0] * inv : 0.f;
        float v1 = (s0 + 1 <= t) ? srow[s0 + 1] * inv : 0.f;
        *(__half2*)(arow + s0) = __floats2half2_rn(v0, v1);
    }
}

// ---------------- mma.sync GEMM: C = alpha * A * B^T (single-product fp16) ----------------
// CTA tile 128x128, 256 threads (8 warps, 2m x 4n of 64x32), BK=32,
// 4-stage smem pipeline, compact XOR-swizzled smem, 1 sync/chunk, 2 CTAs/SM.
#define TILEB  8192                 // 128 rows x 64B
#define STAGEB (2 * TILEB)          // 16384: A, B
#define NSTAGE 4
#define SMEM_TOT (NSTAGE * STAGEB)  // 65536

template<int CSKIP, bool CK, int EPI>   // EPI: 0 -> f32 C, 1 -> single fp16 C
__global__ __launch_bounds__(256, 2)
void mmagemm(const h16* __restrict__ A, const h16* __restrict__ B,
             float* __restrict__ Cf, h16* __restrict__ Ch,
             int M, int N, int K, int ldA, int ldB, int ldC,
             long sA, long sB, long sC, float alpha)
{
    extern __shared__ char smc[];
    const int bx = blockIdx.x, by = blockIdx.y, z = blockIdx.z;
    if (CSKIP && bx > by) return;   // tile fully above causal diagonal

    A += (size_t)z * sA;
    B += (size_t)z * sB;

    const int Keff = CK ? min(K, (by + 1) * 128) : K;
    const int nc = Keff >> 5;
    const int tid = threadIdx.x, wid = tid >> 5, lane = tid & 31;
    const int m0 = by * 128, n0 = bx * 128;
    const uint32_t smb = smem_u32(smc);

    // ---- load mapping: thread -> row tid>>1, chunks {(tid&1)*2, (tid&1)*2+1} ----
    const int lrow = tid >> 1;
    const int lc0  = (tid & 1) * 2;
    const int lswz = (lrow >> 1) & 3;
    const uint32_t dRow = (uint32_t)(lrow * 64);
    const uint32_t d0 = dRow + (uint32_t)((lc0 ^ lswz) << 4);
    const uint32_t d1 = dRow + (uint32_t)(((lc0 + 1) ^ lswz) << 4);
    const h16* gA = A + (size_t)(m0 + lrow) * ldA + lc0 * 8;
    const h16* gB = B + (size_t)(n0 + lrow) * ldB + lc0 * 8;

#define PREFETCH(c, s) do { \
        uint32_t b_ = smb + (uint32_t)(s) * STAGEB; \
        const h16* p_ = gA + (size_t)(c) * 32; \
        CPA(b_ + d0, p_); CPA(b_ + d1, p_ + 8); \
        p_ = gB + (size_t)(c) * 32; \
        CPA(b_ + TILEB + d0, p_); CPA(b_ + TILEB + d1, p_ + 8); \
        CP_COMMIT(); \
    } while (0)

    // ---- compute mapping: warp tile 64x32 (2m x 4n warps) ----
    const int wm = (wid & 1) * 64;
    const int wn = (wid >> 1) * 32;
    const int aRowL = lane & 15;
    const int aSwz = (aRowL >> 1) & 3;
    const int aCh = lane >> 4;
    const uint32_t aBase = (uint32_t)((wm + aRowL) * 64);
    const int bRowL = (lane & 7) + ((lane & 16) >> 1);
    const int bSwz = (bRowL >> 1) & 3;
    const int bCh = (lane & 8) >> 3;
    const uint32_t bBase = (uint32_t)((wn + bRowL) * 64);

    float acc[4][4][4];
    #pragma unroll
    for (int i = 0; i < 4; i++)
        #pragma unroll
        for (int j = 0; j < 4; j++)
            #pragma unroll
            for (int q = 0; q < 4; q++) acc[i][j][q] = 0.f;

    PREFETCH(0, 0);
    if (nc > 1) PREFETCH(1, 1);
    if (nc > 2) PREFETCH(2, 2);

    int st = 0;
    for (int c = 0; c < nc; ++c) {
        const int rem = nc - 1 - c;
        if (rem >= 2)      CP_WAIT(2);
        else if (rem == 1) CP_WAIT(1);
        else               CP_WAIT(0);
        __syncthreads();
        if (c + 3 < nc) {
            int ps = st + 3; if (ps >= NSTAGE) ps -= NSTAGE;
            PREFETCH(c + 3, ps);
        }

        const uint32_t base = smb + (uint32_t)st * STAGEB;
        #pragma unroll
        for (int half = 0; half < 2; half++) {
            const uint32_t aCol = (uint32_t)(((half * 2 + aCh) ^ aSwz) << 4);
            const uint32_t bCol = (uint32_t)(((half * 2 + bCh) ^ bSwz) << 4);

            uint32_t ah[4][4];
            #pragma unroll
            for (int mi = 0; mi < 4; mi++)
                LDSM4(ah[mi], base + aBase + mi * 1024 + aCol);
            uint32_t bh[4][2];
            #pragma unroll
            for (int nb = 0; nb < 2; nb++) {
                uint32_t r4[4];
                LDSM4(r4, base + TILEB + bBase + nb * 1024 + bCol);
                bh[nb * 2][0] = r4[0]; bh[nb * 2][1] = r4[1];
                bh[nb * 2 + 1][0] = r4[2]; bh[nb * 2 + 1][1] = r4[3];
            }
            #pragma unroll
            for (int mi = 0; mi < 4; mi++)
                #pragma unroll
                for (int ni = 0; ni < 4; ni++)
                    MMA(acc[mi][ni], ah[mi], bh[ni]);
        }
        if (++st == NSTAGE) st = 0;
    }
#undef PREFETCH

    // ---- epilogue ----
    const int er = lane >> 2, ec = (lane & 3) * 2;
    if (EPI == 0) {
        float* Cz = Cf + (size_t)z * sC;
        #pragma unroll
        for (int mi = 0; mi < 4; mi++) {
            const int r1 = m0 + wm + mi * 16 + er;
            #pragma unroll
            for (int ni = 0; ni < 4; ni++) {
                const int c1 = n0 + wn + ni * 8 + ec;
                if (c1 < N) {
                    float2 v0 = make_float2(acc[mi][ni][0] * alpha, acc[mi][ni][1] * alpha);
                    float2 v1 = make_float2(acc[mi][ni][2] * alpha, acc[mi][ni][3] * alpha);
                    *(float2*)(Cz + (size_t)r1 * ldC + c1) = v0;
                    *(float2*)(Cz + (size_t)(r1 + 8) * ldC + c1) = v1;
                }
            }
        }
    } else {
        h16* Cz = Ch + (size_t)z * sC;
        #pragma unroll
        for (int mi = 0; mi < 4; mi++) {
            const int r1 = m0 + wm + mi * 16 + er;
            #pragma unroll
            for (int ni = 0; ni < 4; ni++) {
                const int c1 = n0 + wn + ni * 8 + ec;
                if (c1 < N) {
                    *(__half2*)(Cz + (size_t)r1 * ldC + c1) =
                        __floats2half2_rn(acc[mi][ni][0] * alpha, acc[mi][ni][1] * alpha);
                    *(__half2*)(Cz + (size_t)(r1 + 8) * ldC + c1) =
                        __floats2half2_rn(acc[mi][ni][2] * alpha, acc[mi][ni][3] * alpha);
                }
            }
        }
    }
}

// ---------------- Launch ----------------
extern "C" void kernel_launch(void* const* d_in, const int* in_sizes, int n_in,
                              void* d_out, int out_size)
{
    (void)in_sizes; (void)n_in; (void)out_size;
    const float* x     = (const float*)d_in[0];
    const float* cosT  = (const float*)d_in[1];
    const float* sinT  = (const float*)d_in[2];
    const float* Wqkv  = (const float*)d_in[3];
    const float* Wqdec = (const float*)d_in[4];
    const float* Wout  = (const float*)d_in[5];
    float* out = (float*)d_out;

    float *lat, *qbuf, *scores;
    h16 *xh, *wqkvT, *cqh, *wqdecT, *qh, *kh, *vT, *attnh, *yh, *woutT;
    cudaGetSymbolAddress((void**)&lat, g_lat);
    cudaGetSymbolAddress((void**)&qbuf, g_qbuf);
    cudaGetSymbolAddress((void**)&scores, g_scores);
    cudaGetSymbolAddress((void**)&xh, g_xh);
    cudaGetSymbolAddress((void**)&wqkvT, g_wqkvT);
    cudaGetSymbolAddress((void**)&cqh, g_cqh);
    cudaGetSymbolAddress((void**)&wqdecT, g_wqdecT);
    cudaGetSymbolAddress((void**)&qh, g_qh);
    cudaGetSymbolAddress((void**)&kh, g_kh);
    cudaGetSymbolAddress((void**)&vT, g_vT);
    cudaGetSymbolAddress((void**)&attnh, g_attnh);
    cudaGetSymbolAddress((void**)&yh, g_yh);
    cudaGetSymbolAddress((void**)&woutT, g_woutT);

    cudaFuncSetAttribute((const void*)mmagemm<0, false, 0>,
                         cudaFuncAttributeMaxDynamicSharedMemorySize, SMEM_TOT);
    cudaFuncSetAttribute((const void*)mmagemm<1, false, 0>,
                         cudaFuncAttributeMaxDynamicSharedMemorySize, SMEM_TOT);
    cudaFuncSetAttribute((const void*)mmagemm<0, true, 1>,
                         cudaFuncAttributeMaxDynamicSharedMemorySize, SMEM_TOT);

    const float scale = 0.04419417382415922f;   // 1/sqrt(512)

    // 0-2: input conversions
    conv_x<<<8192, 256>>>(x, xh);
    conv_wqkv<<<dim3(NPAD1 / 32, NEMBD / 32), 256>>>(Wqkv, wqkvT);
    conv_w2<<<NQDBLK + NWOBLK, 256>>>(Wqdec, wqdecT, Wout, woutT);

    // 3: G1: lat = x @ Wqkv  [2048 x 1600]
    mmagemm<0, false, 0><<<dim3(13, 16, 1), 256, SMEM_TOT>>>(
        xh, wqkvT, lat, nullptr,
        T_SEQ, LATD, NEMBD, NEMBD, NEMBD, LATD, 0, 0, 0, 1.f);

    // 4: conversions from lat (fused)
    conv_lat<<<NCQBLK + NVTBLK, 256>>>(lat, cqh, vT);

    // 5: G2: qbuf = c_q @ Wqdec  [2048 x 9216]
    mmagemm<0, false, 0><<<dim3(72, 16, 1), 256, SMEM_TOT>>>(
        cqh, wqdecT, qbuf, nullptr,
        T_SEQ, QTOT, QLOW, QLOW, QLOW, QTOT, 0, 0, 0, 1.f);

    // 6: RoPE: k single, q single
    rope_pack_kernel<<<T_SEQ, 256>>>(lat, qbuf, cosT, sinT, kh, qh);

    // 7: scores[h] = scale * q_h @ k^T, causal tile skip
    mmagemm<1, false, 0><<<dim3(16, 16, NHEAD), 256, SMEM_TOT>>>(
        qh, kh, scores, nullptr,
        T_SEQ, T_SEQ, QKHS, QTOT, QKHS, T_SEQ,
        (long)QKHS, 0, (long)T_SEQ * T_SEQ, scale);

    // 8: softmax -> single fp16 attn
    softmax_kernel<<<dim3(T_SEQ, NHEAD), 256>>>(scores, attnh);

    // 9: PV: y_h = attn_h @ v (K causal-truncated), fp16 epilogue
    mmagemm<0, true, 1><<<dim3(4, 16, NHEAD), 256, SMEM_TOT>>>(
        attnh, vT, nullptr, yh,
        T_SEQ, KVLOW, T_SEQ, T_SEQ, T_SEQ, YTOT,
        (long)T_SEQ * T_SEQ, 0, (long)KVLOW, 1.f);

    // 10: G3: out = y @ Wout  [2048 x 2048]
    mmagemm<0, false, 0><<<dim3(16, 16, 1), 256, SMEM_TOT>>>(
        yh, woutT, out, nullptr,
        T_SEQ, NEMBD, YTOT, YTOT, YTOT, NEMBD, 0, 0, 0, 1.f);
}